// round 16
// baseline (speedup 1.0000x reference)
#include <cuda_runtime.h>
#include <cstdint>

#define B_  4
#define S_  2048
#define D_  1024
#define H_  16
#define DH_ 64
#define NSPLIT 8

// scratch
__device__ float    g_qkv[(size_t)B_ * S_ * 3 * D_];  // [B*S, 3D], tf32-rounded
__device__ uint16_t g_Xh[(size_t)B_ * S_ * D_];       // bf16 hi/lo planes
__device__ uint16_t g_Xl[(size_t)B_ * S_ * D_];
__device__ uint16_t g_W1h[(size_t)3 * D_ * D_];
__device__ uint16_t g_W1l[(size_t)3 * D_ * D_];
__device__ uint16_t g_W2h[(size_t)D_ * D_];
__device__ uint16_t g_W2l[(size_t)D_ * D_];
__device__ uint16_t g_atth[(size_t)B_ * S_ * D_];     // scrambled att, hi/lo
__device__ uint16_t g_attl[(size_t)B_ * S_ * D_];
__device__ float    g_wp[(size_t)B_ * H_ * NSPLIT * 64 * 64];
__device__ float    g_wf[(size_t)B_ * H_ * 64 * 64];

// ---------------------------------------------------------------------------
__device__ __forceinline__ uint32_t s2u(const void* p) {
    return (uint32_t)__cvta_generic_to_shared(p);
}
__device__ __forceinline__ void cp16(uint32_t dst, const void* src) {
    asm volatile("cp.async.cg.shared.global [%0], [%1], 16;\n" :: "r"(dst), "l"(src));
}
__device__ __forceinline__ void cp_commit() {
    asm volatile("cp.async.commit_group;\n" ::: "memory");
}
__device__ __forceinline__ void cp_wait1() {
    asm volatile("cp.async.wait_group 1;\n" ::: "memory");
}
__device__ __forceinline__ float round_tf32(float v) {
    uint32_t r;
    asm("cvt.rna.tf32.f32 %0, %1;\n" : "=r"(r) : "f"(v));
    return __uint_as_float(r);
}
// pack two floats -> bf16x2 (c0 in low half = lower address)
__device__ __forceinline__ uint32_t bf16pack(float c0, float c1) {
    uint32_t r;
    asm("cvt.rn.bf16x2.f32 %0, %1, %2;\n" : "=r"(r) : "f"(c1), "f"(c0));
    return r;
}
// residual v - bf16_rn(v), exact in fp32
__device__ __forceinline__ float bf16res(float v) {
    uint32_t hb;
    asm("{\n\t.reg .b16 h, z;\n\tmov.b16 z, 0;\n\t"
        "cvt.rn.bf16.f32 h, %1;\n\tmov.b32 %0, {z, h};\n\t}"
        : "=r"(hb) : "f"(v));
    return v - __uint_as_float(hb);
}
__device__ __forceinline__ void mma_bf16(
    float* c, uint32_t a0, uint32_t a1, uint32_t a2, uint32_t a3,
    uint32_t b0, uint32_t b1)
{
    asm volatile(
        "mma.sync.aligned.m16n8k16.row.col.f32.bf16.bf16.f32 "
        "{%0,%1,%2,%3}, {%4,%5,%6,%7}, {%8,%9}, {%0,%1,%2,%3};\n"
        : "+f"(c[0]), "+f"(c[1]), "+f"(c[2]), "+f"(c[3])
        : "r"(a0), "r"(a1), "r"(a2), "r"(a3), "r"(b0), "r"(b1));
}
__device__ __forceinline__ void mma_tf32(
    float& c0, float& c1, float& c2, float& c3,
    float a0, float a1, float a2, float a3,
    float b0, float b1)
{
    asm volatile(
        "mma.sync.aligned.m16n8k8.row.col.f32.tf32.tf32.f32 "
        "{%0,%1,%2,%3}, {%4,%5,%6,%7}, {%8,%9}, {%0,%1,%2,%3};\n"
        : "+f"(c0), "+f"(c1), "+f"(c2), "+f"(c3)
        : "r"(__float_as_uint(a0)), "r"(__float_as_uint(a1)),
          "r"(__float_as_uint(a2)), "r"(__float_as_uint(a3)),
          "r"(__float_as_uint(b0)), "r"(__float_as_uint(b1)));
}

// ---------------------------------------------------------------------------
// Split inputs into bf16 hi/lo planes.
// ---------------------------------------------------------------------------
#define NX   (B_ * S_ * D_ / 4)
#define NW1  (3 * D_ * D_ / 4)
#define NW2  (D_ * D_ / 4)

__global__ void __launch_bounds__(256) split_inputs(
    const float4* __restrict__ X, const float4* __restrict__ W1,
    const float4* __restrict__ W2,
    uint2* __restrict__ Xh, uint2* __restrict__ Xl,
    uint2* __restrict__ W1h, uint2* __restrict__ W1l,
    uint2* __restrict__ W2h, uint2* __restrict__ W2l)
{
    int i = blockIdx.x * blockDim.x + threadIdx.x;
    const float4* src; uint2 *hd, *ld; int idx;
    if (i < NX)            { src = X;  hd = Xh;  ld = Xl;  idx = i; }
    else if (i < NX + NW1) { src = W1; hd = W1h; ld = W1l; idx = i - NX; }
    else if (i < NX + NW1 + NW2) { src = W2; hd = W2h; ld = W2l; idx = i - NX - NW1; }
    else return;
    float4 v = src[idx];
    uint2 hv, lv;
    hv.x = bf16pack(v.x, v.y);
    hv.y = bf16pack(v.z, v.w);
    lv.x = bf16pack(bf16res(v.x), bf16res(v.y));
    lv.y = bf16pack(bf16res(v.z), bf16res(v.w));
    hd[idx] = hv;
    ld[idx] = lv;
}

// ---------------------------------------------------------------------------
// bf16 3-term split GEMM (NT): C = A @ W^T + bias  (A,W given as hi/lo planes)
// CTA 128x256, warp 64x64, BK=32, 3-stage cp.async.
// smem rows: 64B data + 16B pad (80B pitch) -> conflict-free fragments.
// ---------------------------------------------------------------------------
#define TM 128
#define TN 256
#define TK 32
#define NSTAGE 3
#define AH_OFF 0
#define AL_OFF (128 * 80)                 // 10240
#define BH_OFF (2 * 128 * 80)             // 20480
#define BL_OFF (2 * 128 * 80 + 256 * 80)  // 40960
#define STG_BYTES (2 * 128 * 80 + 2 * 256 * 80)   // 61440
#define GEMM_SMEM (NSTAGE * STG_BYTES)            // 184320

__device__ __forceinline__ void load_stage(
    const uint16_t* __restrict__ Ah, const uint16_t* __restrict__ Al,
    const uint16_t* __restrict__ Bh, const uint16_t* __restrict__ Bl,
    int K, int bm, int bn, int k0, uint32_t sbase, int tid)
{
#pragma unroll
    for (int i = 0; i < 2; i++) {
        int cid = tid + i * 256;
        int row = cid >> 2, slot = cid & 3;
        size_t goff = (size_t)(bm + row) * K + k0 + slot * 8;
        uint32_t d = sbase + row * 80 + slot * 16;
        cp16(d + AH_OFF, Ah + goff);
        cp16(d + AL_OFF, Al + goff);
    }
#pragma unroll
    for (int i = 0; i < 4; i++) {
        int cid = tid + i * 256;
        int row = cid >> 2, slot = cid & 3;
        size_t goff = (size_t)(bn + row) * K + k0 + slot * 8;
        uint32_t d = sbase + row * 80 + slot * 16;
        cp16(d + BH_OFF, Bh + goff);
        cp16(d + BL_OFF, Bl + goff);
    }
}

__global__ void __launch_bounds__(256, 1) gemm_bf16(
    const uint16_t* __restrict__ Ah, const uint16_t* __restrict__ Al,
    const uint16_t* __restrict__ Bh, const uint16_t* __restrict__ Bl,
    const float* __restrict__ bias, float* __restrict__ C,
    int M, int N, int K, int round_out)
{
    extern __shared__ char smem[];
    const uint32_t sbase = s2u(smem);

    const int tid = threadIdx.x;
    const int wid = tid >> 5;
    const int lid = tid & 31;
    const int wm  = wid & 1;          // 2 warp rows -> 64 M
    const int wn  = wid >> 1;         // 4 warp cols -> 64 N
    const int g   = lid >> 2;
    const int t   = lid & 3;
    const int bm  = blockIdx.y * TM;
    const int bn  = blockIdx.x * TN;

    float acc[4][8][4];
#pragma unroll
    for (int i = 0; i < 4; i++)
#pragma unroll
        for (int j = 0; j < 8; j++)
#pragma unroll
            for (int q = 0; q < 4; q++) acc[i][j][q] = 0.f;

    const int NCHUNK = K / TK;

#pragma unroll
    for (int p = 0; p < NSTAGE - 1; p++) {
        load_stage(Ah, Al, Bh, Bl, K, bm, bn, p * TK, sbase + p * STG_BYTES, tid);
        cp_commit();
    }

    for (int kc = 0; kc < NCHUNK; kc++) {
        cp_wait1();
        __syncthreads();

        const char* sb = smem + (kc % NSTAGE) * STG_BYTES;

#pragma unroll
        for (int kk = 0; kk < 2; kk++) {
            const int kb = kk * 32 + 4 * t;

            uint32_t bhf[8][2], blf[8][2];
#pragma unroll
            for (int nb = 0; nb < 8; nb++) {
                const char* p = sb + BH_OFF + (wn * 64 + nb * 8 + g) * 80 + kb;
                bhf[nb][0] = *(const uint32_t*)p;
                bhf[nb][1] = *(const uint32_t*)(p + 16);
                const char* q = p + (BL_OFF - BH_OFF);
                blf[nb][0] = *(const uint32_t*)q;
                blf[nb][1] = *(const uint32_t*)(q + 16);
            }

#pragma unroll
            for (int mb = 0; mb < 4; mb++) {
                const char* pa = sb + AH_OFF + (wm * 64 + mb * 16 + g) * 80 + kb;
                uint32_t ah0 = *(const uint32_t*)pa;
                uint32_t ah1 = *(const uint32_t*)(pa + 8 * 80);
                uint32_t ah2 = *(const uint32_t*)(pa + 16);
                uint32_t ah3 = *(const uint32_t*)(pa + 8 * 80 + 16);
                const char* qa = pa + (AL_OFF - AH_OFF);
                uint32_t al0 = *(const uint32_t*)qa;
                uint32_t al1 = *(const uint32_t*)(qa + 8 * 80);
                uint32_t al2 = *(const uint32_t*)(qa + 16);
                uint32_t al3 = *(const uint32_t*)(qa + 8 * 80 + 16);
#pragma unroll
                for (int nb = 0; nb < 8; nb++) {
                    mma_bf16(acc[mb][nb], ah0, ah1, ah2, ah3, bhf[nb][0], bhf[nb][1]);
                    mma_bf16(acc[mb][nb], ah0, ah1, ah2, ah3, blf[nb][0], blf[nb][1]);
                    mma_bf16(acc[mb][nb], al0, al1, al2, al3, bhf[nb][0], bhf[nb][1]);
                }
            }
        }

        const int nk = kc + NSTAGE - 1;
        if (nk < NCHUNK)
            load_stage(Ah, Al, Bh, Bl, K, bm, bn, nk * TK,
                       sbase + (nk % NSTAGE) * STG_BYTES, tid);
        cp_commit();
    }

    // epilogue
#pragma unroll
    for (int i = 0; i < 4; i++) {
        const int row0 = bm + wm * 64 + i * 16 + g;
#pragma unroll
        for (int j = 0; j < 8; j++) {
            const int col = bn + wn * 64 + j * 8 + 2 * t;
            const float b0 = bias[col];
            const float b1 = bias[col + 1];
            float2 v0 = make_float2(acc[i][j][0] + b0, acc[i][j][1] + b1);
            float2 v1 = make_float2(acc[i][j][2] + b0, acc[i][j][3] + b1);
            if (round_out) {
                v0.x = round_tf32(v0.x); v0.y = round_tf32(v0.y);
                v1.x = round_tf32(v1.x); v1.y = round_tf32(v1.y);
            }
            *(float2*)&C[(size_t)row0 * N + col] = v0;
            *(float2*)&C[(size_t)(row0 + 8) * N + col] = v1;
        }
    }
}

// ---------------------------------------------------------------------------
// Attention stage A (tensor tf32): partial scores. grid (64, NSPLIT).
// ---------------------------------------------------------------------------
#define PAD 68

__global__ void __launch_bounds__(256) attn_scores(
    const float* __restrict__ qkv, float* __restrict__ wp)
{
    __shared__ float sm[2 * 64 * PAD];
    float* S0 = sm;
    float* S1 = sm + 64 * PAD;

    const int bh = blockIdx.x;
    const int split = blockIdx.y;
    const int b  = bh >> 4;
    const int h  = bh & 15;
    const float* base = qkv + (size_t)b * S_ * (3 * D_);

    const int tid = threadIdx.x;
    const int wid = tid >> 5;
    const int lid = tid & 31;
    const int g   = lid >> 2;
    const int t   = lid & 3;
    const int wm  = wid & 3;
    const int wn  = wid >> 2;
    const int dA  = wm * 16 + g;
    const int nB  = wn * 32 + g;

    float acc[4][4];
#pragma unroll
    for (int j = 0; j < 4; j++)
#pragma unroll
        for (int q = 0; q < 4; q++) acc[j][q] = 0.f;

    const int sbeg = split * (S_ / NSPLIT);
    for (int s0 = sbeg; s0 < sbeg + S_ / NSPLIT; s0 += 64) {
#pragma unroll
        for (int jj = 0; jj < 4; jj++) {
            int l  = tid + jj * 256;
            int ss = l >> 4;
            int c4 = (l & 15) * 4;
            const float* gp = base + (size_t)(s0 + ss) * (3 * D_) + h * DH_ + c4;
            *(float4*)&S0[ss * PAD + c4] = *(const float4*)gp;
            *(float4*)&S1[ss * PAD + c4] = *(const float4*)(gp + D_);
        }
        __syncthreads();

#pragma unroll
        for (int ko = 0; ko < 8; ko++) {
            const int kr = ko * 8 + t;
            float a0 = S0[kr * PAD + dA];
            float a1 = S0[kr * PAD + dA + 8];
            float a2 = S0[(kr + 4) * PAD + dA];
            float a3 = S0[(kr + 4) * PAD + dA + 8];
#pragma unroll
            for (int j = 0; j < 4; j++) {
                float b0 = S1[kr * PAD + nB + j * 8];
                float b1 = S1[(kr + 4) * PAD + nB + j * 8];
                mma_tf32(acc[j][0], acc[j][1], acc[j][2], acc[j][3],
                         a0, a1, a2, a3, b0, b1);
            }
        }
        __syncthreads();
    }

    float* wt = wp + ((size_t)(bh * NSPLIT + split)) * 4096;
    const int col0 = wn * 32 + 2 * t;
#pragma unroll
    for (int j = 0; j < 4; j++) {
        *(float2*)&wt[dA * 64 + col0 + j * 8]       = make_float2(acc[j][0], acc[j][1]);
        *(float2*)&wt[(dA + 8) * 64 + col0 + j * 8] = make_float2(acc[j][2], acc[j][3]);
    }
}

// ---------------------------------------------------------------------------
// Softmax: parallel partial-reduce + row softmax. grid 64, block 256.
// ---------------------------------------------------------------------------
__global__ void __launch_bounds__(256) attn_softmax(
    const float* __restrict__ wp, float* __restrict__ wf)
{
    __shared__ float sw[64 * PAD];
    const int bh = blockIdx.x;
    const int tid = threadIdx.x;
    const float* wt = wp + (size_t)bh * NSPLIT * 4096;
    const float scale = rsqrtf((float)S_);

    for (int l = tid; l < 1024; l += 256) {
        int d  = l >> 4;
        int e4 = (l & 15) * 4;
        float4 r = make_float4(0.f, 0.f, 0.f, 0.f);
#pragma unroll
        for (int p = 0; p < NSPLIT; p++) {
            float4 q = *(const float4*)&wt[(size_t)p * 4096 + d * 64 + e4];
            r.x += q.x; r.y += q.y; r.z += q.z; r.w += q.w;
        }
        r.x *= scale; r.y *= scale; r.z *= scale; r.w *= scale;
        *(float4*)&sw[d * PAD + e4] = r;
    }
    __syncthreads();

    if (tid < 64) {
        float* row = &sw[tid * PAD];
        float m = -1e30f;
#pragma unroll
        for (int e = 0; e < 64; e++) m = fmaxf(m, row[e]);
        float s = 0.f;
#pragma unroll
        for (int e = 0; e < 64; e++) { float v = expf(row[e] - m); row[e] = v; s += v; }
        float inv = 1.f / s;
        float* wo = wf + (size_t)bh * 4096 + tid * 64;
#pragma unroll
        for (int e4 = 0; e4 < 16; e4++) {
            float4 v;
            v.x = round_tf32(row[e4 * 4 + 0] * inv);
            v.y = round_tf32(row[e4 * 4 + 1] * inv);
            v.z = round_tf32(row[e4 * 4 + 2] * inv);
            v.w = round_tf32(row[e4 * 4 + 3] * inv);
            *(float4*)&wo[e4 * 4] = v;
        }
    }
}

// ---------------------------------------------------------------------------
// Attention stage B (tensor tf32): o = w @ V; scrambled bf16 hi/lo store
// (feeds bf16 GEMM3). grid (64, NSPLIT).
// ---------------------------------------------------------------------------
__global__ void __launch_bounds__(256) attn_out(
    const float* __restrict__ qkv, const float* __restrict__ wf,
    uint16_t* __restrict__ atth, uint16_t* __restrict__ attl)
{
    __shared__ float sm[2 * 64 * PAD];
    float* S0 = sm;
    float* S1 = sm + 64 * PAD;

    const int bh = blockIdx.x;
    const int split = blockIdx.y;
    const int b  = bh >> 4;
    const int h  = bh & 15;
    const float* base = qkv + (size_t)b * S_ * (3 * D_);

    const int tid = threadIdx.x;
    const int wid = tid >> 5;
    const int lid = tid & 31;
    const int g   = lid >> 2;
    const int t   = lid & 3;
    const int wm  = wid & 3;
    const int wn  = wid >> 2;

    const float* wsrc = wf + (size_t)bh * 4096;
    for (int l = tid; l < 1024; l += 256) {
        int d  = l >> 4;
        int e4 = (l & 15) * 4;
        *(float4*)&S0[d * PAD + e4] = *(const float4*)&wsrc[d * 64 + e4];
    }
    __syncthreads();

    float aw[8][4];
#pragma unroll
    for (int ko = 0; ko < 8; ko++) {
        const int kr = ko * 8 + t;
        aw[ko][0] = S0[(wm * 16 + g) * PAD + kr];
        aw[ko][1] = S0[(wm * 16 + g + 8) * PAD + kr];
        aw[ko][2] = S0[(wm * 16 + g) * PAD + kr + 4];
        aw[ko][3] = S0[(wm * 16 + g + 8) * PAD + kr + 4];
    }

    const int sbeg = split * (S_ / NSPLIT);
    const int d  = wm * 16 + g;
    const int sl = wn * 32 + 2 * t;

    for (int s0 = sbeg; s0 < sbeg + S_ / NSPLIT; s0 += 64) {
#pragma unroll
        for (int jj = 0; jj < 4; jj++) {
            int l  = tid + jj * 256;
            int ss = l >> 4;
            int e4 = (l & 15) * 4;
            *(float4*)&S1[ss * PAD + e4] =
                *(const float4*)(base + (size_t)(s0 + ss) * (3 * D_) + 2 * D_ + h * DH_ + e4);
        }
        __syncthreads();

        float acc[4][4];
#pragma unroll
        for (int j = 0; j < 4; j++)
#pragma unroll
            for (int q = 0; q < 4; q++) acc[j][q] = 0.f;

#pragma unroll
        for (int ko = 0; ko < 8; ko++) {
            const int kr = ko * 8 + t;
#pragma unroll
            for (int j = 0; j < 4; j++) {
                const float* vr = &S1[(wn * 32 + j * 8 + g) * PAD];
                float b0 = vr[kr];
                float b1 = vr[kr + 4];
                mma_tf32(acc[j][0], acc[j][1], acc[j][2], acc[j][3],
                         aw[ko][0], aw[ko][1], aw[ko][2], aw[ko][3], b0, b1);
            }
        }
        __syncthreads();

        // scrambled bf16 hi/lo store: att[b][h*128 + 2d + (s>>10)][s & 1023]
#pragma unroll
        for (int j = 0; j < 4; j++) {
            int s = s0 + sl + j * 8;
            int col = s & 1023;         // even
            int hi  = s >> 10;
            size_t r0 = ((size_t)b * S_ + h * 128 + d * 2 + hi) * D_ + col;
            size_t r1 = ((size_t)b * S_ + h * 128 + (d + 8) * 2 + hi) * D_ + col;
            *(uint32_t*)(atth + r0) = bf16pack(acc[j][0], acc[j][1]);
            *(uint32_t*)(attl + r0) = bf16pack(bf16res(acc[j][0]), bf16res(acc[j][1]));
            *(uint32_t*)(atth + r1) = bf16pack(acc[j][2], acc[j][3]);
            *(uint32_t*)(attl + r1) = bf16pack(bf16res(acc[j][2]), bf16res(acc[j][3]));
        }
    }
}

// ---------------------------------------------------------------------------
extern "C" void kernel_launch(void* const* d_in, const int* in_sizes, int n_in,
                              void* d_out, int out_size)
{
    const float* X  = (const float*)d_in[0];
    const float* W1 = (const float*)d_in[1];
    const float* b1 = (const float*)d_in[2];
    const float* W2 = (const float*)d_in[3];
    const float* b2 = (const float*)d_in[4];
    float* out = (float*)d_out;

    float *qkv, *wp, *wf;
    uint16_t *Xh, *Xl, *W1h, *W1l, *W2h, *W2l, *atth, *attl;
    cudaGetSymbolAddress((void**)&qkv,  g_qkv);
    cudaGetSymbolAddress((void**)&wp,   g_wp);
    cudaGetSymbolAddress((void**)&wf,   g_wf);
    cudaGetSymbolAddress((void**)&Xh,   g_Xh);
    cudaGetSymbolAddress((void**)&Xl,   g_Xl);
    cudaGetSymbolAddress((void**)&W1h,  g_W1h);
    cudaGetSymbolAddress((void**)&W1l,  g_W1l);
    cudaGetSymbolAddress((void**)&W2h,  g_W2h);
    cudaGetSymbolAddress((void**)&W2l,  g_W2l);
    cudaGetSymbolAddress((void**)&atth, g_atth);
    cudaGetSymbolAddress((void**)&attl, g_attl);

    cudaFuncSetAttribute(gemm_bf16, cudaFuncAttributeMaxDynamicSharedMemorySize, GEMM_SMEM);

    // 0) split inputs into bf16 hi/lo planes
    int total4 = NX + NW1 + NW2;
    split_inputs<<<(total4 + 255) / 256, 256>>>(
        (const float4*)X, (const float4*)W1, (const float4*)W2,
        (uint2*)Xh, (uint2*)Xl, (uint2*)W1h, (uint2*)W1l, (uint2*)W2h, (uint2*)W2l);

    // 1) GEMM1: QKV = X @ W1^T + b1, tf32-rounded   [8192, 3072]
    dim3 g1(3 * D_ / TN, (B_ * S_) / TM);
    gemm_bf16<<<g1, 256, GEMM_SMEM>>>(Xh, Xl, W1h, W1l, b1, qkv, B_ * S_, 3 * D_, D_, 1);

    // 2) attention (tf32 tensor-core)
    attn_scores<<<dim3(B_ * H_, NSPLIT), 256>>>(qkv, wp);
    attn_softmax<<<B_ * H_, 256>>>(wp, wf);
    attn_out<<<dim3(B_ * H_, NSPLIT), 256>>>(qkv, wf, atth, attl);

    // 3) GEMM3: out = att @ W2^T + b2  [8192, 1024]
    dim3 g3(D_ / TN, (B_ * S_) / TM);
    gemm_bf16<<<g3, 256, GEMM_SMEM>>>(atth, attl, W2h, W2l, b2, out, B_ * S_, D_, D_, 0);
}

// round 17
// speedup vs baseline: 2.0851x; 2.0851x over previous
#include <cuda_runtime.h>
#include <cstdint>

#define B_  4
#define S_  2048
#define D_  1024
#define H_  16
#define DH_ 64
#define NSPLIT 8

// scratch
__device__ float    g_qkv[(size_t)B_ * S_ * 3 * D_];  // [B*S, 3D], tf32-rounded
__device__ uint16_t g_Xh[(size_t)B_ * S_ * D_];       // fp16 X
__device__ uint16_t g_W1h[(size_t)3 * D_ * D_];       // fp16 W1
__device__ uint16_t g_W2h[(size_t)D_ * D_];           // fp16 W2
__device__ uint16_t g_atth[(size_t)B_ * S_ * D_];     // scrambled att, fp16
__device__ float    g_wp[(size_t)B_ * H_ * NSPLIT * 64 * 64];
__device__ float    g_wf[(size_t)B_ * H_ * 64 * 64];

// ---------------------------------------------------------------------------
__device__ __forceinline__ uint32_t s2u(const void* p) {
    return (uint32_t)__cvta_generic_to_shared(p);
}
__device__ __forceinline__ void cp16(uint32_t dst, const void* src) {
    asm volatile("cp.async.cg.shared.global [%0], [%1], 16;\n" :: "r"(dst), "l"(src));
}
__device__ __forceinline__ void cp_commit() {
    asm volatile("cp.async.commit_group;\n" ::: "memory");
}
__device__ __forceinline__ void cp_wait1() {
    asm volatile("cp.async.wait_group 1;\n" ::: "memory");
}
__device__ __forceinline__ float round_tf32(float v) {
    uint32_t r;
    asm("cvt.rna.tf32.f32 %0, %1;\n" : "=r"(r) : "f"(v));
    return __uint_as_float(r);
}
// pack two floats -> f16x2 (c0 in low half = lower address)
__device__ __forceinline__ uint32_t f16pack(float c0, float c1) {
    uint32_t r;
    asm("cvt.rn.f16x2.f32 %0, %1, %2;\n" : "=r"(r) : "f"(c1), "f"(c0));
    return r;
}
__device__ __forceinline__ void mma_f16(
    float* c, uint32_t a0, uint32_t a1, uint32_t a2, uint32_t a3,
    uint32_t b0, uint32_t b1)
{
    asm volatile(
        "mma.sync.aligned.m16n8k16.row.col.f32.f16.f16.f32 "
        "{%0,%1,%2,%3}, {%4,%5,%6,%7}, {%8,%9}, {%0,%1,%2,%3};\n"
        : "+f"(c[0]), "+f"(c[1]), "+f"(c[2]), "+f"(c[3])
        : "r"(a0), "r"(a1), "r"(a2), "r"(a3), "r"(b0), "r"(b1));
}
__device__ __forceinline__ void mma_tf32(
    float& c0, float& c1, float& c2, float& c3,
    float a0, float a1, float a2, float a3,
    float b0, float b1)
{
    asm volatile(
        "mma.sync.aligned.m16n8k8.row.col.f32.tf32.tf32.f32 "
        "{%0,%1,%2,%3}, {%4,%5,%6,%7}, {%8,%9}, {%0,%1,%2,%3};\n"
        : "+f"(c0), "+f"(c1), "+f"(c2), "+f"(c3)
        : "r"(__float_as_uint(a0)), "r"(__float_as_uint(a1)),
          "r"(__float_as_uint(a2)), "r"(__float_as_uint(a3)),
          "r"(__float_as_uint(b0)), "r"(__float_as_uint(b1)));
}

// ---------------------------------------------------------------------------
// Convert inputs to fp16.
// ---------------------------------------------------------------------------
#define NX   (B_ * S_ * D_ / 4)
#define NW1  (3 * D_ * D_ / 4)
#define NW2  (D_ * D_ / 4)

__global__ void __launch_bounds__(256) conv_inputs(
    const float4* __restrict__ X, const float4* __restrict__ W1,
    const float4* __restrict__ W2,
    uint2* __restrict__ Xh, uint2* __restrict__ W1h, uint2* __restrict__ W2h)
{
    int i = blockIdx.x * blockDim.x + threadIdx.x;
    const float4* src; uint2* hd; int idx;
    if (i < NX)            { src = X;  hd = Xh;  idx = i; }
    else if (i < NX + NW1) { src = W1; hd = W1h; idx = i - NX; }
    else if (i < NX + NW1 + NW2) { src = W2; hd = W2h; idx = i - NX - NW1; }
    else return;
    float4 v = src[idx];
    uint2 hv;
    hv.x = f16pack(v.x, v.y);
    hv.y = f16pack(v.z, v.w);
    hd[idx] = hv;
}

// ---------------------------------------------------------------------------
// fp16 single-term GEMM (NT): C = A @ W^T + bias  (A,W fp16)
// CTA 128x256, warp 64x64, BK=32, 3-stage cp.async.
// smem rows: 64B data + 16B pad (80B pitch) -> conflict-free fragments.
// ---------------------------------------------------------------------------
#define TM 128
#define TN 256
#define TK 32
#define NSTAGE 3
#define A_OFF 0
#define B_OFF (128 * 80)                  // 10240
#define STG_BYTES (128 * 80 + 256 * 80)   // 30720
#define GEMM_SMEM (NSTAGE * STG_BYTES)    // 92160

__device__ __forceinline__ void load_stage(
    const uint16_t* __restrict__ Ah, const uint16_t* __restrict__ Bh,
    int K, int bm, int bn, int k0, uint32_t sbase, int tid)
{
#pragma unroll
    for (int i = 0; i < 2; i++) {
        int cid = tid + i * 256;
        int row = cid >> 2, slot = cid & 3;
        size_t goff = (size_t)(bm + row) * K + k0 + slot * 8;
        cp16(sbase + A_OFF + row * 80 + slot * 16, Ah + goff);
    }
#pragma unroll
    for (int i = 0; i < 4; i++) {
        int cid = tid + i * 256;
        int row = cid >> 2, slot = cid & 3;
        size_t goff = (size_t)(bn + row) * K + k0 + slot * 8;
        cp16(sbase + B_OFF + row * 80 + slot * 16, Bh + goff);
    }
}

__global__ void __launch_bounds__(256, 1) gemm_f16(
    const uint16_t* __restrict__ Ah, const uint16_t* __restrict__ Bh,
    const float* __restrict__ bias, float* __restrict__ C,
    int M, int N, int K, int round_out)
{
    extern __shared__ char smem[];
    const uint32_t sbase = s2u(smem);

    const int tid = threadIdx.x;
    const int wid = tid >> 5;
    const int lid = tid & 31;
    const int wm  = wid & 1;          // 2 warp rows -> 64 M
    const int wn  = wid >> 1;         // 4 warp cols -> 64 N
    const int g   = lid >> 2;
    const int t   = lid & 3;
    const int bm  = blockIdx.y * TM;
    const int bn  = blockIdx.x * TN;

    float acc[4][8][4];
#pragma unroll
    for (int i = 0; i < 4; i++)
#pragma unroll
        for (int j = 0; j < 8; j++)
#pragma unroll
            for (int q = 0; q < 4; q++) acc[i][j][q] = 0.f;

    const int NCHUNK = K / TK;

#pragma unroll
    for (int p = 0; p < NSTAGE - 1; p++) {
        load_stage(Ah, Bh, K, bm, bn, p * TK, sbase + p * STG_BYTES, tid);
        cp_commit();
    }

    for (int kc = 0; kc < NCHUNK; kc++) {
        cp_wait1();
        __syncthreads();

        const char* sb = smem + (kc % NSTAGE) * STG_BYTES;

#pragma unroll
        for (int kk = 0; kk < 2; kk++) {
            const int kb = kk * 32 + 4 * t;

            uint32_t bf[8][2];
#pragma unroll
            for (int nb = 0; nb < 8; nb++) {
                const char* p = sb + B_OFF + (wn * 64 + nb * 8 + g) * 80 + kb;
                bf[nb][0] = *(const uint32_t*)p;
                bf[nb][1] = *(const uint32_t*)(p + 16);
            }

#pragma unroll
            for (int mb = 0; mb < 4; mb++) {
                const char* pa = sb + A_OFF + (wm * 64 + mb * 16 + g) * 80 + kb;
                uint32_t a0 = *(const uint32_t*)pa;
                uint32_t a1 = *(const uint32_t*)(pa + 8 * 80);
                uint32_t a2 = *(const uint32_t*)(pa + 16);
                uint32_t a3 = *(const uint32_t*)(pa + 8 * 80 + 16);
#pragma unroll
                for (int nb = 0; nb < 8; nb++)
                    mma_f16(acc[mb][nb], a0, a1, a2, a3, bf[nb][0], bf[nb][1]);
            }
        }

        const int nk = kc + NSTAGE - 1;
        if (nk < NCHUNK)
            load_stage(Ah, Bh, K, bm, bn, nk * TK,
                       sbase + (nk % NSTAGE) * STG_BYTES, tid);
        cp_commit();
    }

    // epilogue
#pragma unroll
    for (int i = 0; i < 4; i++) {
        const int row0 = bm + wm * 64 + i * 16 + g;
#pragma unroll
        for (int j = 0; j < 8; j++) {
            const int col = bn + wn * 64 + j * 8 + 2 * t;
            const float b0 = bias[col];
            const float b1 = bias[col + 1];
            float2 v0 = make_float2(acc[i][j][0] + b0, acc[i][j][1] + b1);
            float2 v1 = make_float2(acc[i][j][2] + b0, acc[i][j][3] + b1);
            if (round_out) {
                v0.x = round_tf32(v0.x); v0.y = round_tf32(v0.y);
                v1.x = round_tf32(v1.x); v1.y = round_tf32(v1.y);
            }
            *(float2*)&C[(size_t)row0 * N + col] = v0;
            *(float2*)&C[(size_t)(row0 + 8) * N + col] = v1;
        }
    }
}

// ---------------------------------------------------------------------------
// Attention stage A (tensor tf32): partial scores. grid (64, NSPLIT).
// ---------------------------------------------------------------------------
#define PAD 68

__global__ void __launch_bounds__(256) attn_scores(
    const float* __restrict__ qkv, float* __restrict__ wp)
{
    __shared__ float sm[2 * 64 * PAD];
    float* S0 = sm;
    float* S1 = sm + 64 * PAD;

    const int bh = blockIdx.x;
    const int split = blockIdx.y;
    const int b  = bh >> 4;
    const int h  = bh & 15;
    const float* base = qkv + (size_t)b * S_ * (3 * D_);

    const int tid = threadIdx.x;
    const int wid = tid >> 5;
    const int lid = tid & 31;
    const int g   = lid >> 2;
    const int t   = lid & 3;
    const int wm  = wid & 3;
    const int wn  = wid >> 2;
    const int dA  = wm * 16 + g;
    const int nB  = wn * 32 + g;

    float acc[4][4];
#pragma unroll
    for (int j = 0; j < 4; j++)
#pragma unroll
        for (int q = 0; q < 4; q++) acc[j][q] = 0.f;

    const int sbeg = split * (S_ / NSPLIT);
    for (int s0 = sbeg; s0 < sbeg + S_ / NSPLIT; s0 += 64) {
#pragma unroll
        for (int jj = 0; jj < 4; jj++) {
            int l  = tid + jj * 256;
            int ss = l >> 4;
            int c4 = (l & 15) * 4;
            const float* gp = base + (size_t)(s0 + ss) * (3 * D_) + h * DH_ + c4;
            *(float4*)&S0[ss * PAD + c4] = *(const float4*)gp;
            *(float4*)&S1[ss * PAD + c4] = *(const float4*)(gp + D_);
        }
        __syncthreads();

#pragma unroll
        for (int ko = 0; ko < 8; ko++) {
            const int kr = ko * 8 + t;
            float a0 = S0[kr * PAD + dA];
            float a1 = S0[kr * PAD + dA + 8];
            float a2 = S0[(kr + 4) * PAD + dA];
            float a3 = S0[(kr + 4) * PAD + dA + 8];
#pragma unroll
            for (int j = 0; j < 4; j++) {
                float b0 = S1[kr * PAD + nB + j * 8];
                float b1 = S1[(kr + 4) * PAD + nB + j * 8];
                mma_tf32(acc[j][0], acc[j][1], acc[j][2], acc[j][3],
                         a0, a1, a2, a3, b0, b1);
            }
        }
        __syncthreads();
    }

    float* wt = wp + ((size_t)(bh * NSPLIT + split)) * 4096;
    const int col0 = wn * 32 + 2 * t;
#pragma unroll
    for (int j = 0; j < 4; j++) {
        *(float2*)&wt[dA * 64 + col0 + j * 8]       = make_float2(acc[j][0], acc[j][1]);
        *(float2*)&wt[(dA + 8) * 64 + col0 + j * 8] = make_float2(acc[j][2], acc[j][3]);
    }
}

// ---------------------------------------------------------------------------
// Softmax: parallel partial-reduce + row softmax. grid 64, block 256.
// ---------------------------------------------------------------------------
__global__ void __launch_bounds__(256) attn_softmax(
    const float* __restrict__ wp, float* __restrict__ wf)
{
    __shared__ float sw[64 * PAD];
    const int bh = blockIdx.x;
    const int tid = threadIdx.x;
    const float* wt = wp + (size_t)bh * NSPLIT * 4096;
    const float scale = rsqrtf((float)S_);

    for (int l = tid; l < 1024; l += 256) {
        int d  = l >> 4;
        int e4 = (l & 15) * 4;
        float4 r = make_float4(0.f, 0.f, 0.f, 0.f);
#pragma unroll
        for (int p = 0; p < NSPLIT; p++) {
            float4 q = *(const float4*)&wt[(size_t)p * 4096 + d * 64 + e4];
            r.x += q.x; r.y += q.y; r.z += q.z; r.w += q.w;
        }
        r.x *= scale; r.y *= scale; r.z *= scale; r.w *= scale;
        *(float4*)&sw[d * PAD + e4] = r;
    }
    __syncthreads();

    if (tid < 64) {
        float* row = &sw[tid * PAD];
        float m = -1e30f;
#pragma unroll
        for (int e = 0; e < 64; e++) m = fmaxf(m, row[e]);
        float s = 0.f;
#pragma unroll
        for (int e = 0; e < 64; e++) { float v = expf(row[e] - m); row[e] = v; s += v; }
        float inv = 1.f / s;
        float* wo = wf + (size_t)bh * 4096 + tid * 64;
#pragma unroll
        for (int e4 = 0; e4 < 16; e4++) {
            float4 v;
            v.x = round_tf32(row[e4 * 4 + 0] * inv);
            v.y = round_tf32(row[e4 * 4 + 1] * inv);
            v.z = round_tf32(row[e4 * 4 + 2] * inv);
            v.w = round_tf32(row[e4 * 4 + 3] * inv);
            *(float4*)&wo[e4 * 4] = v;
        }
    }
}

// ---------------------------------------------------------------------------
// Attention stage B (tensor tf32): o = w @ V; scrambled fp16 store
// (feeds fp16 GEMM3). grid (64, NSPLIT).
// ---------------------------------------------------------------------------
__global__ void __launch_bounds__(256) attn_out(
    const float* __restrict__ qkv, const float* __restrict__ wf,
    uint16_t* __restrict__ atth)
{
    __shared__ float sm[2 * 64 * PAD];
    float* S0 = sm;
    float* S1 = sm + 64 * PAD;

    const int bh = blockIdx.x;
    const int split = blockIdx.y;
    const int b  = bh >> 4;
    const int h  = bh & 15;
    const float* base = qkv + (size_t)b * S_ * (3 * D_);

    const int tid = threadIdx.x;
    const int wid = tid >> 5;
    const int lid = tid & 31;
    const int g   = lid >> 2;
    const int t   = lid & 3;
    const int wm  = wid & 3;
    const int wn  = wid >> 2;

    const float* wsrc = wf + (size_t)bh * 4096;
    for (int l = tid; l < 1024; l += 256) {
        int d  = l >> 4;
        int e4 = (l & 15) * 4;
        *(float4*)&S0[d * PAD + e4] = *(const float4*)&wsrc[d * 64 + e4];
    }
    __syncthreads();

    float aw[8][4];
#pragma unroll
    for (int ko = 0; ko < 8; ko++) {
        const int kr = ko * 8 + t;
        aw[ko][0] = S0[(wm * 16 + g) * PAD + kr];
        aw[ko][1] = S0[(wm * 16 + g + 8) * PAD + kr];
        aw[ko][2] = S0[(wm * 16 + g) * PAD + kr + 4];
        aw[ko][3] = S0[(wm * 16 + g + 8) * PAD + kr + 4];
    }

    const int sbeg = split * (S_ / NSPLIT);
    const int d  = wm * 16 + g;
    const int sl = wn * 32 + 2 * t;

    for (int s0 = sbeg; s0 < sbeg + S_ / NSPLIT; s0 += 64) {
#pragma unroll
        for (int jj = 0; jj < 4; jj++) {
            int l  = tid + jj * 256;
            int ss = l >> 4;
            int e4 = (l & 15) * 4;
            *(float4*)&S1[ss * PAD + e4] =
                *(const float4*)(base + (size_t)(s0 + ss) * (3 * D_) + 2 * D_ + h * DH_ + e4);
        }
        __syncthreads();

        float acc[4][4];
#pragma unroll
        for (int j = 0; j < 4; j++)
#pragma unroll
            for (int q = 0; q < 4; q++) acc[j][q] = 0.f;

#pragma unroll
        for (int ko = 0; ko < 8; ko++) {
            const int kr = ko * 8 + t;
#pragma unroll
            for (int j = 0; j < 4; j++) {
                const float* vr = &S1[(wn * 32 + j * 8 + g) * PAD];
                float b0 = vr[kr];
                float b1 = vr[kr + 4];
                mma_tf32(acc[j][0], acc[j][1], acc[j][2], acc[j][3],
                         aw[ko][0], aw[ko][1], aw[ko][2], aw[ko][3], b0, b1);
            }
        }
        __syncthreads();

        // scrambled fp16 store: att[b][h*128 + 2d + (s>>10)][s & 1023]
#pragma unroll
        for (int j = 0; j < 4; j++) {
            int s = s0 + sl + j * 8;
            int col = s & 1023;         // even
            int hi  = s >> 10;
            size_t r0 = ((size_t)b * S_ + h * 128 + d * 2 + hi) * D_ + col;
            size_t r1 = ((size_t)b * S_ + h * 128 + (d + 8) * 2 + hi) * D_ + col;
            *(uint32_t*)(atth + r0) = f16pack(acc[j][0], acc[j][1]);
            *(uint32_t*)(atth + r1) = f16pack(acc[j][2], acc[j][3]);
        }
    }
}

// ---------------------------------------------------------------------------
extern "C" void kernel_launch(void* const* d_in, const int* in_sizes, int n_in,
                              void* d_out, int out_size)
{
    const float* X  = (const float*)d_in[0];
    const float* W1 = (const float*)d_in[1];
    const float* b1 = (const float*)d_in[2];
    const float* W2 = (const float*)d_in[3];
    const float* b2 = (const float*)d_in[4];
    float* out = (float*)d_out;

    float *qkv, *wp, *wf;
    uint16_t *Xh, *W1h, *W2h, *atth;
    cudaGetSymbolAddress((void**)&qkv,  g_qkv);
    cudaGetSymbolAddress((void**)&wp,   g_wp);
    cudaGetSymbolAddress((void**)&wf,   g_wf);
    cudaGetSymbolAddress((void**)&Xh,   g_Xh);
    cudaGetSymbolAddress((void**)&W1h,  g_W1h);
    cudaGetSymbolAddress((void**)&W2h,  g_W2h);
    cudaGetSymbolAddress((void**)&atth, g_atth);

    cudaFuncSetAttribute(gemm_f16, cudaFuncAttributeMaxDynamicSharedMemorySize, GEMM_SMEM);

    // 0) convert inputs to fp16
    int total4 = NX + NW1 + NW2;
    conv_inputs<<<(total4 + 255) / 256, 256>>>(
        (const float4*)X, (const float4*)W1, (const float4*)W2,
        (uint2*)Xh, (uint2*)W1h, (uint2*)W2h);

    // 1) GEMM1: QKV = X @ W1^T + b1, tf32-rounded   [8192, 3072]
    dim3 g1(3 * D_ / TN, (B_ * S_) / TM);
    gemm_f16<<<g1, 256, GEMM_SMEM>>>(Xh, W1h, b1, qkv, B_ * S_, 3 * D_, D_, 1);

    // 2) attention (tf32 tensor-core)
    attn_scores<<<dim3(B_ * H_, NSPLIT), 256>>>(qkv, wp);
    attn_softmax<<<B_ * H_, 256>>>(wp, wf);
    attn_out<<<dim3(B_ * H_, NSPLIT), 256>>>(qkv, wf, atth);

    // 3) GEMM3: out = att @ W2^T + b2  [8192, 1024]
    dim3 g3(D_ / TN, (B_ * S_) / TM);
    gemm_f16<<<g3, 256, GEMM_SMEM>>>(atth, W2h, b2, out, B_ * S_, D_, D_, 0);
}